// round 4
// baseline (speedup 1.0000x reference)
#include <cuda_runtime.h>

#define TPB    384
#define NODES  32
#define XS     292                 // floats per node per chunk buffer (288 + 4 pad)
#define XBUF   (NODES * XS)        // 9344 floats per buffer
#define SM_W0  (2 * XBUF)          // w1_0: 6144 floats
#define SM_W1  (SM_W0 + 6144)      // w1_1: 2048
#define SM_W2  (SM_W1 + 2048)      // w1_2: 2048
#define SM_W2S (SM_W2 + 2048)      // w2_0|w2_1|w2_2: 48
#define SM_FLOATS (SM_W2S + 48)    // 28976 floats = 115904 bytes

__global__ void __launch_bounds__(TPB, 1)
readout_kernel(const float* __restrict__ x,
               const float* __restrict__ w1_0, const float* __restrict__ w1_1,
               const float* __restrict__ w1_2, const float* __restrict__ w2_0,
               const float* __restrict__ w2_1, const float* __restrict__ w2_2,
               float* __restrict__ out, int n)
{
    extern __shared__ float sm[];
    const int tid = threadIdx.x;
    const int node0 = blockIdx.x * NODES;

    // ---- stage weights to shared ----
    for (int i = tid; i < 6144; i += TPB) sm[SM_W0 + i] = w1_0[i];
    for (int i = tid; i < 2048; i += TPB) sm[SM_W1 + i] = w1_1[i];
    for (int i = tid; i < 2048; i += TPB) sm[SM_W2 + i] = w1_2[i];
    if (tid < 16) {
        sm[SM_W2S + tid]      = w2_0[tid];
        sm[SM_W2S + 16 + tid] = w2_1[tid];
        sm[SM_W2S + 32 + tid] = w2_2[tid];
    }

    // ---- x staging precompute: 6 float4 per thread per chunk ----
    // per node-chunk: 72 float4 = x0(8) + x1(24) + x2(40)
    int snd[6], sbase[6], scoef[6], sloc[6];
#pragma unroll
    for (int k = 0; k < 6; ++k) {
        int f = tid + k * TPB;
        int nd = f / 72, r = f - nd * 72;
        snd[k] = nd;
        if (r < 8)       { sbase[k] = 4 * r;              scoef[k] = 32;  sloc[k] = 4 * r; }
        else if (r < 32) { sbase[k] = 128 + 4 * (r - 8);  scoef[k] = 96;  sloc[k] = 32 + 4 * (r - 8); }
        else             { sbase[k] = 512 + 4 * (r - 32); scoef[k] = 160; sloc[k] = 128 + 4 * (r - 32); }
    }
    float4 st[6];
    auto ldg = [&](int c) {
#pragma unroll
        for (int k = 0; k < 6; ++k) {
            int gn = node0 + snd[k];
            if (gn < n) st[k] = *(const float4*)(x + (size_t)gn * 1152 + sbase[k] + scoef[k] * c);
            else        st[k] = make_float4(0.f, 0.f, 0.f, 0.f);
        }
    };
    auto sts = [&](int b) {
#pragma unroll
        for (int k = 0; k < 6; ++k)
            *(float4*)(sm + b * XBUF + snd[k] * XS + sloc[k]) = st[k];
    };

    ldg(0); sts(0); ldg(1);
    __syncthreads();

    const int w    = tid >> 5;
    const int lane = tid & 31;
    const int type = w >> 2;    // 0:y0  1:y1  2:y2  (SMSP = w&3 gets one of each)
    const int slot = w & 3;
    const int node = lane;

    float a[20];
#pragma unroll
    for (int i = 0; i < 20; ++i) a[i] = 0.f;

    for (int c = 0; c < 4; ++c) {
        const float* xr = sm + (c & 1) * XBUF + node * XS;

        if (type == 0) {
            // y0: 12 outputs, v0..v0+11
            const int v0 = slot * 12;
#pragma unroll 2
            for (int g = 0; g < 8; ++g) {
                float4 xv = *(const float4*)(xr + 4 * g);
                const float* xe = (const float*)&xv;
                int ub = (c * 32 + 4 * g) * 48 + v0;
#pragma unroll
                for (int du = 0; du < 4; ++du) {
                    float xs_ = xe[du];
                    const float4* wp = (const float4*)(sm + SM_W0 + ub + du * 48);
                    float4 q0 = wp[0], q1 = wp[1], q2 = wp[2];
                    a[0] += xs_ * q0.x; a[1]  += xs_ * q0.y; a[2]  += xs_ * q0.z; a[3]  += xs_ * q0.w;
                    a[4] += xs_ * q1.x; a[5]  += xs_ * q1.y; a[6]  += xs_ * q1.z; a[7]  += xs_ * q1.w;
                    a[8] += xs_ * q2.x; a[9]  += xs_ * q2.y; a[10] += xs_ * q2.z; a[11] += xs_ * q2.w;
                }
            }
        } else if (type == 1) {
            // y1: v0..v0+3, i=0..2
            const int v0 = slot * 4;
#pragma unroll 2
            for (int g = 0; g < 8; ++g) {
                const float4* xp = (const float4*)(xr + 32 + 12 * g);
                float4 q0 = xp[0], q1 = xp[1], q2 = xp[2];
                float xe[12] = { q0.x,q0.y,q0.z,q0.w, q1.x,q1.y,q1.z,q1.w, q2.x,q2.y,q2.z,q2.w };
                int ub = (c * 32 + 4 * g) * 16 + v0;
#pragma unroll
                for (int du = 0; du < 4; ++du) {
                    float4 wv = *(const float4*)(sm + SM_W1 + ub + du * 16);
                    const float* we = (const float*)&wv;
#pragma unroll
                    for (int vv = 0; vv < 4; ++vv)
#pragma unroll
                        for (int i = 0; i < 3; ++i)
                            a[vv * 3 + i] += xe[du * 3 + i] * we[vv];
                }
            }
        } else {
            // y2: v0..v0+3, i=0..4
            const int v0 = slot * 4;
#pragma unroll 2
            for (int g = 0; g < 8; ++g) {
                const float4* xp = (const float4*)(xr + 128 + 20 * g);
                float4 q0 = xp[0], q1 = xp[1], q2 = xp[2], q3 = xp[3], q4 = xp[4];
                float xe[20] = { q0.x,q0.y,q0.z,q0.w, q1.x,q1.y,q1.z,q1.w,
                                 q2.x,q2.y,q2.z,q2.w, q3.x,q3.y,q3.z,q3.w,
                                 q4.x,q4.y,q4.z,q4.w };
                int ub = (c * 32 + 4 * g) * 16 + v0;
#pragma unroll
                for (int du = 0; du < 4; ++du) {
                    float4 wv = *(const float4*)(sm + SM_W2 + ub + du * 16);
                    const float* we = (const float*)&wv;
#pragma unroll
                    for (int vv = 0; vv < 4; ++vv)
#pragma unroll
                        for (int i = 0; i < 5; ++i)
                            a[vv * 5 + i] += xe[du * 5 + i] * we[vv];
                }
            }
        }

        if (c < 3) {
            sts((c + 1) & 1);          // write next chunk (other buffer, no hazard)
            if (c < 2) ldg(c + 2);     // prefetch chunk c+2 into regs
            __syncthreads();
        }
    }

    // ---- dump accumulators into y buffer (reuses buf0 region: 32*177 < 9344) ----
    {
        float* yb = sm + node * 177;
        if (type == 0) {
            const int v0 = slot * 12;
#pragma unroll
            for (int j = 0; j < 12; ++j) yb[v0 + j] = a[j];
        } else if (type == 1) {
            const int v0 = slot * 4;
#pragma unroll
            for (int vv = 0; vv < 4; ++vv)
#pragma unroll
                for (int i = 0; i < 3; ++i)
                    yb[48 + (v0 + vv) * 3 + i] = a[vv * 3 + i];
        } else {
            const int v0 = slot * 4;
#pragma unroll
            for (int vv = 0; vv < 4; ++vv)
#pragma unroll
                for (int i = 0; i < 5; ++i)
                    yb[96 + (v0 + vv) * 5 + i] = a[vv * 5 + i];
        }
    }
    __syncthreads();

    // ---- epilogue: silu + second layer, 9 outputs per node ----
    if (tid < 9 * NODES) {
        const int nd = tid / 9, k = tid - nd * 9;
        const float* yb = sm + nd * 177;
        const float inv_in = 0.08838834764831845f;   // 1/sqrt(128)
        float o = 0.f;
        if (k == 0) {
#pragma unroll
            for (int h = 0; h < 16; ++h) {
                float v = yb[h] * inv_in;
                float s = v / (1.f + __expf(-v));
                o += s * sm[SM_W2S + h];
            }
        } else if (k < 4) {
            const int i = k - 1;
#pragma unroll
            for (int v = 0; v < 16; ++v) {
                float gv = yb[16 + v] * inv_in;
                float g  = gv / (1.f + __expf(-gv));
                o += (yb[48 + v * 3 + i] * inv_in) * g * sm[SM_W2S + 16 + v];
            }
        } else {
            const int i = k - 4;
#pragma unroll
            for (int v = 0; v < 16; ++v) {
                float gv = yb[32 + v] * inv_in;
                float g  = gv / (1.f + __expf(-gv));
                o += (yb[96 + v * 5 + i] * inv_in) * g * sm[SM_W2S + 32 + v];
            }
        }
        const int gn = node0 + nd;
        if (gn < n) out[gn * 9 + k] = o * 0.25f;   // inv_h = 1/sqrt(16)
    }
}

extern "C" void kernel_launch(void* const* d_in, const int* in_sizes, int n_in,
                              void* d_out, int out_size)
{
    const float* x    = (const float*)d_in[0];
    const float* w1_0 = (const float*)d_in[1];
    const float* w1_1 = (const float*)d_in[2];
    const float* w1_2 = (const float*)d_in[3];
    const float* w2_0 = (const float*)d_in[4];
    const float* w2_1 = (const float*)d_in[5];
    const float* w2_2 = (const float*)d_in[6];
    float* out = (float*)d_out;

    const int n = in_sizes[0] / 1152;
    const int smem = SM_FLOATS * (int)sizeof(float);   // 115904 B
    cudaFuncSetAttribute(readout_kernel, cudaFuncAttributeMaxDynamicSharedMemorySize, smem);
    const int blocks = (n + NODES - 1) / NODES;
    readout_kernel<<<blocks, TPB, smem>>>(x, w1_0, w1_1, w1_2, w2_0, w2_1, w2_2, out, n);
}

// round 5
// speedup vs baseline: 1.7698x; 1.7698x over previous
#include <cuda_runtime.h>

#define TPB     384
#define NODES   32
#define KU      16                  // u per chunk
#define NCHUNK  8
#define XS      148                 // floats per node per chunk: x0(16)+x1(48)+x2(80)+pad(4)
#define XBUF    (NODES * XS)        // 4736 floats per buffer
#define OFF_W0  (3 * XBUF)          // 14208  (w1_0: 6144 floats)
#define OFF_W1  (OFF_W0 + 6144)    // 20352  (w1_1: 2048)
#define OFF_W2  (OFF_W1 + 2048)    // 22400  (w1_2: 2048)
#define OFF_W2S (OFF_W2 + 2048)    // 24448  (w2_*: 48)
#define SM_FLOATS (OFF_W2S + 48)   // 24496 floats = 97984 B -> 2 blocks/SM

typedef unsigned long long u64;

__device__ __forceinline__ u64 ffma2(u64 a, u64 b, u64 c) {
    u64 d;
    asm("fma.rn.f32x2 %0, %1, %2, %3;" : "=l"(d) : "l"(a), "l"(b), "l"(c));
    return d;
}
__device__ __forceinline__ u64 dup2(float v) {
    u64 d; unsigned u = __float_as_uint(v);
    asm("mov.b64 %0, {%1, %1};" : "=l"(d) : "r"(u));
    return d;
}
__device__ __forceinline__ void unpack2(u64 a, float& lo, float& hi) {
    lo = __uint_as_float((unsigned)a);
    hi = __uint_as_float((unsigned)(a >> 32));
}

__global__ void __launch_bounds__(TPB, 2)
readout_kernel(const float* __restrict__ x,
               const float* __restrict__ w1_0, const float* __restrict__ w1_1,
               const float* __restrict__ w1_2, const float* __restrict__ w2_0,
               const float* __restrict__ w2_1, const float* __restrict__ w2_2,
               float* __restrict__ out, int n)
{
    extern __shared__ float sm[];
    const int tid = threadIdx.x;
    const int node0 = blockIdx.x * NODES;
    const unsigned smbase = (unsigned)__cvta_generic_to_shared(sm);

    // ---- per-thread cp.async staging constants (3 x 16B per thread per chunk) ----
    // per node per chunk: 36 x 16B = x0(4) + x1(12) + x2(20), all contiguous in gmem
    int snd[3], sb[3], sc[3], ssz[3];
    unsigned sdst[3];
#pragma unroll
    for (int k = 0; k < 3; ++k) {
        int f = tid + k * TPB;
        int nd = f / 36, r = f - nd * 36;
        int dl;
        if (r < 4)       { sb[k] = 4 * r;               sc[k] = 16; dl = 4 * r; }
        else if (r < 16) { sb[k] = 128 + 4 * (r - 4);   sc[k] = 48; dl = 16 + 4 * (r - 4); }
        else             { sb[k] = 512 + 4 * (r - 16);  sc[k] = 80; dl = 64 + 4 * (r - 16); }
        snd[k] = nd;
        sdst[k] = (unsigned)((nd * XS + dl) * 4);
        ssz[k] = (node0 + nd < n) ? 16 : 0;
    }
    auto stage = [&](int c, int buf) {
#pragma unroll
        for (int k = 0; k < 3; ++k) {
            const float* src = x + (size_t)(node0 + snd[k]) * 1152 + sb[k] + sc[k] * c;
            unsigned dst = smbase + (unsigned)(buf * XBUF * 4) + sdst[k];
            asm volatile("cp.async.cg.shared.global [%0], [%1], 16, %2;"
                         :: "r"(dst), "l"(src), "r"(ssz[k]));
        }
    };

    // kick off first two chunks, then stage weights under them
    stage(0, 0); asm volatile("cp.async.commit_group;" ::: "memory");
    stage(1, 1); asm volatile("cp.async.commit_group;" ::: "memory");

    for (int i = tid; i < 6144; i += TPB) sm[OFF_W0 + i] = w1_0[i];
    for (int i = tid; i < 2048; i += TPB) sm[OFF_W1 + i] = w1_1[i];
    for (int i = tid; i < 2048; i += TPB) sm[OFF_W2 + i] = w1_2[i];
    if (tid < 16) {
        sm[OFF_W2S + tid]      = w2_0[tid];
        sm[OFF_W2S + 16 + tid] = w2_1[tid];
        sm[OFF_W2S + 32 + tid] = w2_2[tid];
    }

    const int w    = tid >> 5;
    const int lane = tid & 31;
    const int type = w >> 2;     // 0:y0 1:y1 2:y2 ; SMSP = w&3 gets one warp of each type
    const int slot = w & 3;
    const int node = lane;

    u64 A[10];
#pragma unroll
    for (int i = 0; i < 10; ++i) A[i] = 0ull;

#pragma unroll 1
    for (int c = 0; c < NCHUNK; ++c) {
        if (c == NCHUNK - 1) asm volatile("cp.async.wait_group 0;" ::: "memory");
        else                 asm volatile("cp.async.wait_group 1;" ::: "memory");
        __syncthreads();
        if (c < NCHUNK - 2) {
            stage(c + 2, (c + 2) % 3);
            asm volatile("cp.async.commit_group;" ::: "memory");
        }
        const float* xr = sm + (c % 3) * XBUF + node * XS;
        const int ub0 = KU * c;

        if (type == 0) {
            // y0: outputs v0..v0+11 as 6 f32x2 pairs; weight pairs natural in w1_0
            const int v0 = slot * 12;
#pragma unroll
            for (int g = 0; g < 4; ++g) {
                float4 xv = *(const float4*)(xr + 4 * g);
                float xe[4] = { xv.x, xv.y, xv.z, xv.w };
#pragma unroll
                for (int du = 0; du < 4; ++du) {
                    u64 xs2 = dup2(xe[du]);
                    const ulonglong2* wp =
                        (const ulonglong2*)(sm + OFF_W0 + (ub0 + 4 * g + du) * 48 + v0);
                    ulonglong2 w01 = wp[0], w23 = wp[1], w45 = wp[2];
                    A[0] = ffma2(xs2, w01.x, A[0]); A[1] = ffma2(xs2, w01.y, A[1]);
                    A[2] = ffma2(xs2, w23.x, A[2]); A[3] = ffma2(xs2, w23.y, A[3]);
                    A[4] = ffma2(xs2, w45.x, A[4]); A[5] = ffma2(xs2, w45.y, A[5]);
                }
            }
        } else if (type == 1) {
            // y1: v pairs (v0,v0+1),(v0+2,v0+3) x i=0..2
            const int v0 = slot * 4;
#pragma unroll
            for (int g = 0; g < 4; ++g) {
                const float4* xp = (const float4*)(xr + 16 + 12 * g);
                float4 q0 = xp[0], q1 = xp[1], q2 = xp[2];
                float xe[12] = { q0.x,q0.y,q0.z,q0.w, q1.x,q1.y,q1.z,q1.w,
                                 q2.x,q2.y,q2.z,q2.w };
#pragma unroll
                for (int du = 0; du < 4; ++du) {
                    ulonglong2 wv =
                        *(const ulonglong2*)(sm + OFF_W1 + (ub0 + 4 * g + du) * 16 + v0);
#pragma unroll
                    for (int i = 0; i < 3; ++i) {
                        u64 xs2 = dup2(xe[du * 3 + i]);
                        A[i]     = ffma2(xs2, wv.x, A[i]);
                        A[3 + i] = ffma2(xs2, wv.y, A[3 + i]);
                    }
                }
            }
        } else {
            // y2: v pairs x i=0..4
            const int v0 = slot * 4;
#pragma unroll
            for (int g = 0; g < 4; ++g) {
                const float4* xp = (const float4*)(xr + 64 + 20 * g);
                float4 q0 = xp[0], q1 = xp[1], q2 = xp[2], q3 = xp[3], q4 = xp[4];
                float xe[20] = { q0.x,q0.y,q0.z,q0.w, q1.x,q1.y,q1.z,q1.w,
                                 q2.x,q2.y,q2.z,q2.w, q3.x,q3.y,q3.z,q3.w,
                                 q4.x,q4.y,q4.z,q4.w };
#pragma unroll
                for (int du = 0; du < 4; ++du) {
                    ulonglong2 wv =
                        *(const ulonglong2*)(sm + OFF_W2 + (ub0 + 4 * g + du) * 16 + v0);
#pragma unroll
                    for (int i = 0; i < 5; ++i) {
                        u64 xs2 = dup2(xe[du * 5 + i]);
                        A[i]     = ffma2(xs2, wv.x, A[i]);
                        A[5 + i] = ffma2(xs2, wv.y, A[5 + i]);
                    }
                }
            }
        }
    }

    __syncthreads();   // all compute done before reusing x buffers as y storage

    // ---- dump accumulators to per-node y buffer (177 floats/node, fits in buf space) ----
    {
        float* yb = sm + node * 177;
        if (type == 0) {
            const int v0 = slot * 12;
#pragma unroll
            for (int j = 0; j < 6; ++j) {
                float lo, hi; unpack2(A[j], lo, hi);
                yb[v0 + 2 * j] = lo; yb[v0 + 2 * j + 1] = hi;
            }
        } else if (type == 1) {
            const int v0 = slot * 4;
#pragma unroll
            for (int i = 0; i < 3; ++i) {
                float lo, hi;
                unpack2(A[i], lo, hi);
                yb[48 + (v0 + 0) * 3 + i] = lo; yb[48 + (v0 + 1) * 3 + i] = hi;
                unpack2(A[3 + i], lo, hi);
                yb[48 + (v0 + 2) * 3 + i] = lo; yb[48 + (v0 + 3) * 3 + i] = hi;
            }
        } else {
            const int v0 = slot * 4;
#pragma unroll
            for (int i = 0; i < 5; ++i) {
                float lo, hi;
                unpack2(A[i], lo, hi);
                yb[96 + (v0 + 0) * 5 + i] = lo; yb[96 + (v0 + 1) * 5 + i] = hi;
                unpack2(A[5 + i], lo, hi);
                yb[96 + (v0 + 2) * 5 + i] = lo; yb[96 + (v0 + 3) * 5 + i] = hi;
            }
        }
    }
    __syncthreads();

    // ---- epilogue: silu + second layer, 9 outputs per node ----
    if (tid < 9 * NODES) {
        const int nd = tid / 9, k = tid - nd * 9;
        const float* yb = sm + nd * 177;
        const float inv_in = 0.08838834764831845f;   // 1/sqrt(128)
        float o = 0.f;
        if (k == 0) {
#pragma unroll
            for (int h = 0; h < 16; ++h) {
                float v = yb[h] * inv_in;
                float s = v / (1.f + __expf(-v));
                o += s * sm[OFF_W2S + h];
            }
        } else if (k < 4) {
            const int i = k - 1;
#pragma unroll
            for (int v = 0; v < 16; ++v) {
                float gv = yb[16 + v] * inv_in;
                float g  = gv / (1.f + __expf(-gv));
                o += (yb[48 + v * 3 + i] * inv_in) * g * sm[OFF_W2S + 16 + v];
            }
        } else {
            const int i = k - 4;
#pragma unroll
            for (int v = 0; v < 16; ++v) {
                float gv = yb[32 + v] * inv_in;
                float g  = gv / (1.f + __expf(-gv));
                o += (yb[96 + v * 5 + i] * inv_in) * g * sm[OFF_W2S + 32 + v];
            }
        }
        const int gn = node0 + nd;
        if (gn < n) out[gn * 9 + k] = o * 0.25f;   // 1/sqrt(16)
    }
}

extern "C" void kernel_launch(void* const* d_in, const int* in_sizes, int n_in,
                              void* d_out, int out_size)
{
    const float* x    = (const float*)d_in[0];
    const float* w1_0 = (const float*)d_in[1];
    const float* w1_1 = (const float*)d_in[2];
    const float* w1_2 = (const float*)d_in[3];
    const float* w2_0 = (const float*)d_in[4];
    const float* w2_1 = (const float*)d_in[5];
    const float* w2_2 = (const float*)d_in[6];
    float* out = (float*)d_out;

    const int n = in_sizes[0] / 1152;
    const int smem = SM_FLOATS * (int)sizeof(float);   // 97984 B
    cudaFuncSetAttribute(readout_kernel, cudaFuncAttributeMaxDynamicSharedMemorySize, smem);
    const int blocks = (n + NODES - 1) / NODES;
    readout_kernel<<<blocks, TPB, smem>>>(x, w1_0, w1_1, w1_2, w2_0, w2_1, w2_2, out, n);
}